// round 6
// baseline (speedup 1.0000x reference)
#include <cuda_runtime.h>
#include <math.h>

#define D_MODEL 768
#define D_HID   3072
#define NE      8
#define NTOK    2048
#define NPAIR   (NTOK * 2)        // 4096 (token, slot) pairs
#define MAXPER  2048              // max pairs per expert (top-2 distinct experts)

// ---------------- device scratch (static; no allocation allowed) -------------
__device__ float g_h[(size_t)NPAIR * D_HID];   // 50.3 MB: gelu(x@W1) per pair
__device__ float g_wgt[NPAIR];                 // normalized routing weight per pair
__device__ int   g_list[NE * MAXPER];          // compacted pair ids per expert
__device__ int   g_cnt[NE];                    // pairs routed to each expert

// ---------------- init: zero output + counters --------------------------------
__global__ __launch_bounds__(256)
void init_kernel(float* __restrict__ out) {
    int i = blockIdx.x * blockDim.x + threadIdx.x;
    if (i < NE) g_cnt[i] = 0;
    // 2048*768 floats = 393216 float4, grid sized to cover exactly
    ((float4*)out)[i] = make_float4(0.f, 0.f, 0.f, 0.f);
}

// ---------------- router: one warp per token ----------------------------------
__global__ __launch_bounds__(256)
void router_kernel(const float* __restrict__ x,
                   const float* __restrict__ gw) {
    int gwarp = (blockIdx.x * blockDim.x + threadIdx.x) >> 5;
    int lane  = threadIdx.x & 31;
    if (gwarp >= NTOK) return;
    const float* xr = x + (size_t)gwarp * D_MODEL;

    float acc[NE];
#pragma unroll
    for (int e = 0; e < NE; e++) acc[e] = 0.f;

    for (int d = lane; d < D_MODEL; d += 32) {
        float xv = xr[d];
#pragma unroll
        for (int e = 0; e < NE; e++) acc[e] += xv * gw[d * NE + e];
    }
#pragma unroll
    for (int e = 0; e < NE; e++) {
#pragma unroll
        for (int off = 16; off > 0; off >>= 1)
            acc[e] += __shfl_xor_sync(0xffffffffu, acc[e], off);
    }
    if (lane == 0) {
        // softmax probs (unnormalized exp is enough: normalization cancels in top-2 renorm)
        float mx = acc[0];
#pragma unroll
        for (int e = 1; e < NE; e++) mx = fmaxf(mx, acc[e]);
        float p[NE];
#pragma unroll
        for (int e = 0; e < NE; e++) p[e] = __expf(acc[e] - mx);
        // top-2, ties -> lower index (matches jax.lax.top_k)
        int i0 = 0;
#pragma unroll
        for (int e = 1; e < NE; e++) if (p[e] > p[i0]) i0 = e;
        int i1 = (i0 == 0) ? 1 : 0;
#pragma unroll
        for (int e = 0; e < NE; e++) if (e != i0 && p[e] > p[i1]) i1 = e;
        float s2 = p[i0] + p[i1];
        float w0 = p[i0] / s2, w1 = p[i1] / s2;

        int pr0 = gwarp * 2, pr1 = gwarp * 2 + 1;
        g_wgt[pr0] = w0;
        g_wgt[pr1] = w1;
        int pos0 = atomicAdd(&g_cnt[i0], 1);
        g_list[i0 * MAXPER + pos0] = pr0;
        int pos1 = atomicAdd(&g_cnt[i1], 1);
        g_list[i1 * MAXPER + pos1] = pr1;
    }
}

// ---------------- tiled SGEMM 128x128x16, gathered A rows ---------------------
// GEMM1: h[pair, 0:3072] = gelu( x[tok] @ W1_e + b1_e ), pairs from g_list[e]
__global__ __launch_bounds__(256)
void gemm1_kernel(const float* __restrict__ x,
                  const float* __restrict__ w1,
                  const float* __restrict__ b1) {
    const int e   = blockIdx.z;
    const int cnt = g_cnt[e];
    const int m0  = blockIdx.y * 128;
    if (m0 >= cnt) return;
    const int n0  = blockIdx.x * 128;
    const float* B = w1 + (size_t)e * D_MODEL * D_HID;

    __shared__ float sA[16][128];
    __shared__ float sB[16][128];
    __shared__ int   s_pair[128];
    __shared__ int   s_tok[128];

    const int tx = threadIdx.x, ty = threadIdx.y;
    const int tid = ty * 16 + tx;

    if (tid < 128) {
        int gm = m0 + tid;
        int pr = (gm < cnt) ? g_list[e * MAXPER + gm] : -1;
        s_pair[tid] = pr;
        s_tok[tid]  = (pr >= 0) ? (pr >> 1) : 0;
    }
    __syncthreads();

    float acc[8][8];
#pragma unroll
    for (int i = 0; i < 8; i++)
#pragma unroll
        for (int j = 0; j < 8; j++) acc[i][j] = 0.f;

    const int am = tid >> 1;            // A row this thread loads
    const int ak = (tid & 1) * 8;       // A k-offset
    const int bk = tid >> 4;            // B k-row
    const int bn = (tid & 15) * 8;      // B n-offset

    for (int k0 = 0; k0 < D_MODEL; k0 += 16) {
        // load A (gathered, transposed into smem)
        float4 va0 = make_float4(0.f, 0.f, 0.f, 0.f), va1 = va0;
        if (s_pair[am] >= 0) {
            const float* ar = x + (size_t)s_tok[am] * D_MODEL + k0 + ak;
            va0 = *(const float4*)(ar);
            va1 = *(const float4*)(ar + 4);
        }
        sA[ak + 0][am] = va0.x; sA[ak + 1][am] = va0.y;
        sA[ak + 2][am] = va0.z; sA[ak + 3][am] = va0.w;
        sA[ak + 4][am] = va1.x; sA[ak + 5][am] = va1.y;
        sA[ak + 6][am] = va1.z; sA[ak + 7][am] = va1.w;
        // load B
        {
            const float* br = B + (size_t)(k0 + bk) * D_HID + n0 + bn;
            *(float4*)&sB[bk][bn]     = *(const float4*)(br);
            *(float4*)&sB[bk][bn + 4] = *(const float4*)(br + 4);
        }
        __syncthreads();
#pragma unroll
        for (int k = 0; k < 16; k++) {
            float4 a04 = *(const float4*)&sA[k][ty * 4];
            float4 a14 = *(const float4*)&sA[k][64 + ty * 4];
            float4 b04 = *(const float4*)&sB[k][tx * 4];
            float4 b14 = *(const float4*)&sB[k][64 + tx * 4];
            float a[8] = {a04.x, a04.y, a04.z, a04.w, a14.x, a14.y, a14.z, a14.w};
            float b[8] = {b04.x, b04.y, b04.z, b04.w, b14.x, b14.y, b14.z, b14.w};
#pragma unroll
            for (int i = 0; i < 8; i++)
#pragma unroll
                for (int j = 0; j < 8; j++) acc[i][j] += a[i] * b[j];
        }
        __syncthreads();
    }

    // epilogue: bias + exact erf-GELU, scatter to scratch by pair id
#pragma unroll
    for (int i = 0; i < 8; i++) {
        int r  = (i < 4) ? (ty * 4 + i) : (64 + ty * 4 + (i - 4));
        int gm = m0 + r;
        if (gm >= cnt) continue;
        int pr = s_pair[r];
        float* hrow = g_h + (size_t)pr * D_HID + n0;
#pragma unroll
        for (int j = 0; j < 8; j++) {
            int c = (j < 4) ? (tx * 4 + j) : (64 + tx * 4 + (j - 4));
            float v = acc[i][j] + b1[e * D_HID + n0 + c];
            float g = 0.5f * v * (1.0f + erff(v * 0.70710678118654752f));
            hrow[c] = g;
        }
    }
}

// GEMM2: out[tok] += wgt * ( h[pair] @ W2_e + b2_e )
__global__ __launch_bounds__(256)
void gemm2_kernel(const float* __restrict__ w2,
                  const float* __restrict__ b2,
                  float* __restrict__ out) {
    const int e   = blockIdx.z;
    const int cnt = g_cnt[e];
    const int m0  = blockIdx.y * 128;
    if (m0 >= cnt) return;
    const int n0  = blockIdx.x * 128;
    const float* B = w2 + (size_t)e * D_HID * D_MODEL;

    __shared__ float sA[16][128];
    __shared__ float sB[16][128];
    __shared__ int   s_pair[128];

    const int tx = threadIdx.x, ty = threadIdx.y;
    const int tid = ty * 16 + tx;

    if (tid < 128) {
        int gm = m0 + tid;
        s_pair[tid] = (gm < cnt) ? g_list[e * MAXPER + gm] : -1;
    }
    __syncthreads();

    float acc[8][8];
#pragma unroll
    for (int i = 0; i < 8; i++)
#pragma unroll
        for (int j = 0; j < 8; j++) acc[i][j] = 0.f;

    const int am = tid >> 1;
    const int ak = (tid & 1) * 8;
    const int bk = tid >> 4;
    const int bn = (tid & 15) * 8;

    for (int k0 = 0; k0 < D_HID; k0 += 16) {
        float4 va0 = make_float4(0.f, 0.f, 0.f, 0.f), va1 = va0;
        int pr = s_pair[am];
        if (pr >= 0) {
            const float* ar = g_h + (size_t)pr * D_HID + k0 + ak;
            va0 = *(const float4*)(ar);
            va1 = *(const float4*)(ar + 4);
        }
        sA[ak + 0][am] = va0.x; sA[ak + 1][am] = va0.y;
        sA[ak + 2][am] = va0.z; sA[ak + 3][am] = va0.w;
        sA[ak + 4][am] = va1.x; sA[ak + 5][am] = va1.y;
        sA[ak + 6][am] = va1.z; sA[ak + 7][am] = va1.w;
        {
            const float* br = B + (size_t)(k0 + bk) * D_MODEL + n0 + bn;
            *(float4*)&sB[bk][bn]     = *(const float4*)(br);
            *(float4*)&sB[bk][bn + 4] = *(const float4*)(br + 4);
        }
        __syncthreads();
#pragma unroll
        for (int k = 0; k < 16; k++) {
            float4 a04 = *(const float4*)&sA[k][ty * 4];
            float4 a14 = *(const float4*)&sA[k][64 + ty * 4];
            float4 b04 = *(const float4*)&sB[k][tx * 4];
            float4 b14 = *(const float4*)&sB[k][64 + tx * 4];
            float a[8] = {a04.x, a04.y, a04.z, a04.w, a14.x, a14.y, a14.z, a14.w};
            float b[8] = {b04.x, b04.y, b04.z, b04.w, b14.x, b14.y, b14.z, b14.w};
#pragma unroll
            for (int i = 0; i < 8; i++)
#pragma unroll
                for (int j = 0; j < 8; j++) acc[i][j] += a[i] * b[j];
        }
        __syncthreads();
    }

#pragma unroll
    for (int i = 0; i < 8; i++) {
        int r  = (i < 4) ? (ty * 4 + i) : (64 + ty * 4 + (i - 4));
        int gm = m0 + r;
        if (gm >= cnt) continue;
        int pr  = s_pair[r];
        int tok = pr >> 1;
        float w = g_wgt[pr];
        float* orow = out + (size_t)tok * D_MODEL + n0;
#pragma unroll
        for (int j = 0; j < 8; j++) {
            int c = (j < 4) ? (tx * 4 + j) : (64 + tx * 4 + (j - 4));
            float v = (acc[i][j] + b2[e * D_MODEL + n0 + c]) * w;
            atomicAdd(&orow[c], v);
        }
    }
}

// ---------------- launch ------------------------------------------------------
extern "C" void kernel_launch(void* const* d_in, const int* in_sizes, int n_in,
                              void* d_out, int out_size) {
    const float* x   = (const float*)d_in[0];   // [1,2048,768]
    const float* gw  = (const float*)d_in[1];   // [768,8]
    const float* w1  = (const float*)d_in[2];   // [8,768,3072]
    const float* b1  = (const float*)d_in[3];   // [8,1,3072]
    const float* w2  = (const float*)d_in[4];   // [8,3072,768]
    const float* b2  = (const float*)d_in[5];   // [8,1,768]
    float* out = (float*)d_out;                 // [1,2048,768]

    // 1) zero out + counters: 393216 float4 = 1536 blocks * 256
    init_kernel<<<(NTOK * D_MODEL / 4) / 256, 256>>>(out);
    // 2) router: 2048 warps = 256 blocks * 8 warps
    router_kernel<<<NTOK / 8, 256>>>(x, gw);
    // 3) GEMM1: N tiles 3072/128=24, M tiles 2048/128=16, experts 8
    {
        dim3 grid(D_HID / 128, MAXPER / 128, NE);
        dim3 block(16, 16);
        gemm1_kernel<<<grid, block>>>(x, w1, b1);
    }
    // 4) GEMM2: N tiles 768/128=6
    {
        dim3 grid(D_MODEL / 128, MAXPER / 128, NE);
        dim3 block(16, 16);
        gemm2_kernel<<<grid, block>>>(w2, b2, out);
    }
}

// round 8
// speedup vs baseline: 2.7076x; 2.7076x over previous
#include <cuda_runtime.h>
#include <math.h>
#include <stdint.h>

#define D_MODEL 768
#define D_HID   3072
#define NE      8
#define NTOK    2048
#define NPAIR   (NTOK * 2)
#define MAXPER  2048

// ---------------- device scratch ----------------------------------------------
__device__ float g_h[(size_t)NPAIR * D_HID];   // gelu(x@W1) per routed pair
__device__ float g_wgt[NPAIR];
__device__ int   g_list[NE * MAXPER];
__device__ int   g_cnt[NE];

// ---------------- helpers ------------------------------------------------------
__device__ __forceinline__ uint32_t f2tf32(float v) {
    uint32_t r;
    asm("cvt.rna.tf32.f32 %0, %1;" : "=r"(r) : "f"(v));
    return r;
}
__device__ __forceinline__ void mma_tf32(float* c, uint32_t a0, uint32_t a1,
                                         uint32_t a2, uint32_t a3,
                                         uint32_t b0, uint32_t b1) {
    asm volatile(
        "mma.sync.aligned.m16n8k8.row.col.f32.tf32.tf32.f32 "
        "{%0,%1,%2,%3}, {%4,%5,%6,%7}, {%8,%9}, {%0,%1,%2,%3};"
        : "+f"(c[0]), "+f"(c[1]), "+f"(c[2]), "+f"(c[3])
        : "r"(a0), "r"(a1), "r"(a2), "r"(a3), "r"(b0), "r"(b1));
}
__device__ __forceinline__ float gelu_f(float v) {
    return 0.5f * v * (1.0f + erff(v * 0.70710678118654752f));
}

#define KC   32     // k-chunk
#define LDS_ 36     // padded stride (words): bank = 4*row + k, conflict-light

// ---------------- init --------------------------------------------------------
__global__ __launch_bounds__(256)
void init_kernel(float* __restrict__ out) {
    int i = blockIdx.x * blockDim.x + threadIdx.x;
    if (i < NE) g_cnt[i] = 0;
    ((float4*)out)[i] = make_float4(0.f, 0.f, 0.f, 0.f);
}

// ---------------- router: one warp per token ----------------------------------
__global__ __launch_bounds__(256)
void router_kernel(const float* __restrict__ x, const float* __restrict__ gw) {
    int gwarp = (blockIdx.x * blockDim.x + threadIdx.x) >> 5;
    int lane  = threadIdx.x & 31;
    if (gwarp >= NTOK) return;
    const float* xr = x + (size_t)gwarp * D_MODEL;

    float acc[NE];
#pragma unroll
    for (int e = 0; e < NE; e++) acc[e] = 0.f;
    for (int d = lane; d < D_MODEL; d += 32) {
        float xv = xr[d];
#pragma unroll
        for (int e = 0; e < NE; e++) acc[e] += xv * gw[d * NE + e];
    }
#pragma unroll
    for (int e = 0; e < NE; e++) {
#pragma unroll
        for (int off = 16; off > 0; off >>= 1)
            acc[e] += __shfl_xor_sync(0xffffffffu, acc[e], off);
    }
    if (lane == 0) {
        float mx = acc[0];
#pragma unroll
        for (int e = 1; e < NE; e++) mx = fmaxf(mx, acc[e]);
        float p[NE];
#pragma unroll
        for (int e = 0; e < NE; e++) p[e] = __expf(acc[e] - mx);
        int i0 = 0;
#pragma unroll
        for (int e = 1; e < NE; e++) if (p[e] > p[i0]) i0 = e;
        int i1 = (i0 == 0) ? 1 : 0;
#pragma unroll
        for (int e = 0; e < NE; e++) if (e != i0 && p[e] > p[i1]) i1 = e;
        float s2 = p[i0] + p[i1];
        int pr0 = gwarp * 2, pr1 = gwarp * 2 + 1;
        g_wgt[pr0] = p[i0] / s2;
        g_wgt[pr1] = p[i1] / s2;
        int pos0 = atomicAdd(&g_cnt[i0], 1);
        g_list[i0 * MAXPER + pos0] = pr0;
        int pos1 = atomicAdd(&g_cnt[i1], 1);
        g_list[i1 * MAXPER + pos1] = pr1;
    }
}

// ---------------- GEMM1: h = gelu(x_gathered @ W1_e + b1_e), tf32 mma.sync -----
__global__ __launch_bounds__(256, 2)
void gemm1_mma(const float* __restrict__ x, const float* __restrict__ w1,
               const float* __restrict__ b1) {
    const int e   = blockIdx.z;
    const int cnt = g_cnt[e];
    const int m0  = blockIdx.y * 128;
    if (m0 >= cnt) return;
    const int n0  = blockIdx.x * 128;
    const float* Bw = w1 + (size_t)e * D_MODEL * D_HID;

    __shared__ uint32_t sA[128][LDS_];   // [m][k] tf32 bits
    __shared__ uint32_t sB[128][LDS_];   // [n][k] tf32 bits
    __shared__ int s_pair[128];

    const int tid  = threadIdx.x;
    const int lane = tid & 31, wid = tid >> 5;
    const int wm0 = (wid >> 2) * 64, wn0 = (wid & 3) * 32;

    if (tid < 128) {
        int gm = m0 + tid;
        s_pair[tid] = (gm < cnt) ? g_list[e * MAXPER + gm] : -1;
    }
    __syncthreads();

    // loader roles
    const int lrow = tid >> 1, lk = (tid & 1) * 16;        // A: 2 threads/row
    const int bkr = tid >> 3, bn0_ = (tid & 7) * 16;       // B: 8 threads/k-row
    const int prL = s_pair[lrow];
    const float* arow = x + (size_t)((prL >= 0) ? (prL >> 1) : 0) * D_MODEL + lk;
    const bool av = prL >= 0;

    float acc[4][4][4];
#pragma unroll
    for (int a = 0; a < 4; a++)
#pragma unroll
        for (int b = 0; b < 4; b++)
#pragma unroll
            for (int c = 0; c < 4; c++) acc[a][b][c] = 0.f;

    for (int k0 = 0; k0 < D_MODEL; k0 += KC) {
        // stage A (gathered rows, tf32-rounded)
#pragma unroll
        for (int q = 0; q < 4; q++) {
            float4 v = av ? *(const float4*)(arow + k0 + q * 4) : make_float4(0, 0, 0, 0);
            sA[lrow][lk + q * 4 + 0] = f2tf32(v.x);
            sA[lrow][lk + q * 4 + 1] = f2tf32(v.y);
            sA[lrow][lk + q * 4 + 2] = f2tf32(v.z);
            sA[lrow][lk + q * 4 + 3] = f2tf32(v.w);
        }
        // stage B transposed: w1[k][n] -> sB[n][k]
        {
            const float* bsrc = Bw + (size_t)(k0 + bkr) * D_HID + n0 + bn0_;
#pragma unroll
            for (int q = 0; q < 4; q++) {
                float4 v = *(const float4*)(bsrc + q * 4);
                sB[bn0_ + q * 4 + 0][bkr] = f2tf32(v.x);
                sB[bn0_ + q * 4 + 1][bkr] = f2tf32(v.y);
                sB[bn0_ + q * 4 + 2][bkr] = f2tf32(v.z);
                sB[bn0_ + q * 4 + 3][bkr] = f2tf32(v.w);
            }
        }
        __syncthreads();
#pragma unroll
        for (int ks = 0; ks < KC; ks += 8) {
            uint32_t bf0[4], bf1[4];
#pragma unroll
            for (int ni = 0; ni < 4; ni++) {
                int cB = wn0 + ni * 8 + (lane >> 2);
                bf0[ni] = sB[cB][ks + (lane & 3)];
                bf1[ni] = sB[cB][ks + 4 + (lane & 3)];
            }
#pragma unroll
            for (int mi = 0; mi < 4; mi++) {
                int rA = wm0 + mi * 16 + (lane >> 2);
                uint32_t a0 = sA[rA][ks + (lane & 3)];
                uint32_t a1 = sA[rA + 8][ks + (lane & 3)];
                uint32_t a2 = sA[rA][ks + 4 + (lane & 3)];
                uint32_t a3 = sA[rA + 8][ks + 4 + (lane & 3)];
#pragma unroll
                for (int ni = 0; ni < 4; ni++)
                    mma_tf32(acc[mi][ni], a0, a1, a2, a3, bf0[ni], bf1[ni]);
            }
        }
        __syncthreads();
    }

    // epilogue: bias + erf-GELU -> g_h  (rows r, r+8; cols c, c+1 per frag)
#pragma unroll
    for (int mi = 0; mi < 4; mi++) {
        int r0 = wm0 + mi * 16 + (lane >> 2);
#pragma unroll
        for (int half = 0; half < 2; half++) {
            int r = r0 + half * 8;
            int pr = s_pair[r];
            if (pr < 0) continue;
            float* hrow = g_h + (size_t)pr * D_HID + n0;
#pragma unroll
            for (int ni = 0; ni < 4; ni++) {
                int c = wn0 + ni * 8 + 2 * (lane & 3);
                float2 bb = *(const float2*)(b1 + e * D_HID + n0 + c);
                float2 o;
                o.x = gelu_f(acc[mi][ni][half * 2 + 0] + bb.x);
                o.y = gelu_f(acc[mi][ni][half * 2 + 1] + bb.y);
                *(float2*)(hrow + c) = o;
            }
        }
    }
}

// ---------------- GEMM2: out += wgt * (h_gathered @ W2_e + b2_e) ---------------
__global__ __launch_bounds__(256, 2)
void gemm2_mma(const float* __restrict__ w2, const float* __restrict__ b2,
               float* __restrict__ out) {
    const int e   = blockIdx.z;
    const int cnt = g_cnt[e];
    const int m0  = blockIdx.y * 128;
    if (m0 >= cnt) return;
    const int n0  = blockIdx.x * 128;
    const float* Bw = w2 + (size_t)e * D_HID * D_MODEL;

    __shared__ uint32_t sA[128][LDS_];
    __shared__ uint32_t sB[128][LDS_];
    __shared__ int s_pair[128];

    const int tid  = threadIdx.x;
    const int lane = tid & 31, wid = tid >> 5;
    const int wm0 = (wid >> 2) * 64, wn0 = (wid & 3) * 32;

    if (tid < 128) {
        int gm = m0 + tid;
        s_pair[tid] = (gm < cnt) ? g_list[e * MAXPER + gm] : -1;
    }
    __syncthreads();

    const int lrow = tid >> 1, lk = (tid & 1) * 16;
    const int bkr = tid >> 3, bn0_ = (tid & 7) * 16;
    const int prL = s_pair[lrow];
    const float* arow = g_h + (size_t)((prL >= 0) ? prL : 0) * D_HID + lk;
    const bool av = prL >= 0;

    float acc[4][4][4];
#pragma unroll
    for (int a = 0; a < 4; a++)
#pragma unroll
        for (int b = 0; b < 4; b++)
#pragma unroll
            for (int c = 0; c < 4; c++) acc[a][b][c] = 0.f;

    for (int k0 = 0; k0 < D_HID; k0 += KC) {
#pragma unroll
        for (int q = 0; q < 4; q++) {
            float4 v = av ? *(const float4*)(arow + k0 + q * 4) : make_float4(0, 0, 0, 0);
            sA[lrow][lk + q * 4 + 0] = f2tf32(v.x);
            sA[lrow][lk + q * 4 + 1] = f2tf32(v.y);
            sA[lrow][lk + q * 4 + 2] = f2tf32(v.z);
            sA[lrow][lk + q * 4 + 3] = f2tf32(v.w);
        }
        {
            const float* bsrc = Bw + (size_t)(k0 + bkr) * D_MODEL + n0 + bn0_;
#pragma unroll
            for (int q = 0; q < 4; q++) {
                float4 v = *(const float4*)(bsrc + q * 4);
                sB[bn0_ + q * 4 + 0][bkr] = f2tf32(v.x);
                sB[bn0_ + q * 4 + 1][bkr] = f2tf32(v.y);
                sB[bn0_ + q * 4 + 2][bkr] = f2tf32(v.z);
                sB[bn0_ + q * 4 + 3][bkr] = f2tf32(v.w);
            }
        }
        __syncthreads();
#pragma unroll
        for (int ks = 0; ks < KC; ks += 8) {
            uint32_t bf0[4], bf1[4];
#pragma unroll
            for (int ni = 0; ni < 4; ni++) {
                int cB = wn0 + ni * 8 + (lane >> 2);
                bf0[ni] = sB[cB][ks + (lane & 3)];
                bf1[ni] = sB[cB][ks + 4 + (lane & 3)];
            }
#pragma unroll
            for (int mi = 0; mi < 4; mi++) {
                int rA = wm0 + mi * 16 + (lane >> 2);
                uint32_t a0 = sA[rA][ks + (lane & 3)];
                uint32_t a1 = sA[rA + 8][ks + (lane & 3)];
                uint32_t a2 = sA[rA][ks + 4 + (lane & 3)];
                uint32_t a3 = sA[rA + 8][ks + 4 + (lane & 3)];
#pragma unroll
                for (int ni = 0; ni < 4; ni++)
                    mma_tf32(acc[mi][ni], a0, a1, a2, a3, bf0[ni], bf1[ni]);
            }
        }
        __syncthreads();
    }

    // epilogue: (acc + b2) * wgt, atomicAdd into out
#pragma unroll
    for (int mi = 0; mi < 4; mi++) {
        int r0 = wm0 + mi * 16 + (lane >> 2);
#pragma unroll
        for (int half = 0; half < 2; half++) {
            int r = r0 + half * 8;
            int pr = s_pair[r];
            if (pr < 0) continue;
            int tok = pr >> 1;
            float w = g_wgt[pr];
            float* orow = out + (size_t)tok * D_MODEL + n0;
#pragma unroll
            for (int ni = 0; ni < 4; ni++) {
                int c = wn0 + ni * 8 + 2 * (lane & 3);
                float2 bb = *(const float2*)(b2 + e * D_MODEL + n0 + c);
                atomicAdd(&orow[c],     (acc[mi][ni][half * 2 + 0] + bb.x) * w);
                atomicAdd(&orow[c + 1], (acc[mi][ni][half * 2 + 1] + bb.y) * w);
            }
        }
    }
}

// ---------------- launch ------------------------------------------------------
extern "C" void kernel_launch(void* const* d_in, const int* in_sizes, int n_in,
                              void* d_out, int out_size) {
    const float* x  = (const float*)d_in[0];
    const float* gw = (const float*)d_in[1];
    const float* w1 = (const float*)d_in[2];
    const float* b1 = (const float*)d_in[3];
    const float* w2 = (const float*)d_in[4];
    const float* b2 = (const float*)d_in[5];
    float* out = (float*)d_out;

    init_kernel<<<(NTOK * D_MODEL / 4) / 256, 256>>>(out);
    router_kernel<<<NTOK / 8, 256>>>(x, gw);
    gemm1_mma<<<dim3(D_HID / 128, MAXPER / 128, NE), 256>>>(x, w1, b1);
    gemm2_mma<<<dim3(D_MODEL / 128, MAXPER / 128, NE), 256>>>(w2, b2, out);
}

// round 9
// speedup vs baseline: 4.3857x; 1.6198x over previous
#include <cuda_runtime.h>
#include <math.h>
#include <stdint.h>

#define D_MODEL 768
#define D_HID   3072
#define NE      8
#define NTOK    2048
#define NPAIR   (NTOK * 2)
#define MAXPER  2048

// ---------------- device scratch ----------------------------------------------
__device__ float g_h[(size_t)NPAIR * D_HID];   // tf32-rounded gelu(x@W1) per pair
__device__ float g_x[(size_t)NTOK * D_MODEL];  // tf32-rounded x
__device__ float g_wgt[NPAIR];
__device__ int   g_list[NE * MAXPER];
__device__ int   g_cnt[NE];

// ---------------- helpers ------------------------------------------------------
__device__ __forceinline__ uint32_t smem_u32(const void* p) {
    uint32_t a;
    asm("{ .reg .u64 t; cvta.to.shared.u64 t, %1; cvt.u32.u64 %0, t; }" : "=r"(a) : "l"(p));
    return a;
}
__device__ __forceinline__ uint32_t f2tf32(float v) {
    uint32_t r;
    asm("cvt.rna.tf32.f32 %0, %1;" : "=r"(r) : "f"(v));
    return r;
}
__device__ __forceinline__ uint32_t bits2tf32(uint32_t b) {
    return f2tf32(__uint_as_float(b));
}
__device__ __forceinline__ void mma_tf32(float* c, uint32_t a0, uint32_t a1,
                                         uint32_t a2, uint32_t a3,
                                         uint32_t b0, uint32_t b1) {
    asm volatile(
        "mma.sync.aligned.m16n8k8.row.col.f32.tf32.tf32.f32 "
        "{%0,%1,%2,%3}, {%4,%5,%6,%7}, {%8,%9}, {%0,%1,%2,%3};"
        : "+f"(c[0]), "+f"(c[1]), "+f"(c[2]), "+f"(c[3])
        : "r"(a0), "r"(a1), "r"(a2), "r"(a3), "r"(b0), "r"(b1));
}
__device__ __forceinline__ void cpa16(uint32_t saddr, const void* g, uint32_t nbytes) {
    asm volatile("cp.async.cg.shared.global [%0], [%1], 16, %2;"
                 :: "r"(saddr), "l"(g), "r"(nbytes) : "memory");
}
__device__ __forceinline__ void cpa_commit() {
    asm volatile("cp.async.commit_group;" ::: "memory");
}
__device__ __forceinline__ void cpa_wait2() {
    asm volatile("cp.async.wait_group 2;" ::: "memory");
}
__device__ __forceinline__ float gelu_f(float v) {
    return 0.5f * v * (1.0f + erff(v * 0.70710678118654752f));
}

// smem layout (words): [0..128) s_pair, then 3 stages of (A 128x36 | B 32x136)
#define LDA 36
#define LDB 136
#define A_ST_W (128 * LDA)              // 4608
#define STAGE_W (A_ST_W + 32 * LDB)     // 8960 words = 35840 B
#define SP_W 128
#define NSTAGE 3
#define SMEM_BYTES ((SP_W + NSTAGE * STAGE_W) * 4)   // 108032

// ---------------- init: zero out + counters + pre-round x ---------------------
__global__ __launch_bounds__(256)
void init_kernel(float* __restrict__ out, const float* __restrict__ x) {
    int i = blockIdx.x * blockDim.x + threadIdx.x;
    if (i < NE) g_cnt[i] = 0;
    ((float4*)out)[i] = make_float4(0.f, 0.f, 0.f, 0.f);
    float4 v = ((const float4*)x)[i];
    float4 r;
    r.x = __uint_as_float(f2tf32(v.x));
    r.y = __uint_as_float(f2tf32(v.y));
    r.z = __uint_as_float(f2tf32(v.z));
    r.w = __uint_as_float(f2tf32(v.w));
    ((float4*)g_x)[i] = r;
}

// ---------------- router: one warp per token ----------------------------------
__global__ __launch_bounds__(256)
void router_kernel(const float* __restrict__ x, const float* __restrict__ gw) {
    int gwarp = (blockIdx.x * blockDim.x + threadIdx.x) >> 5;
    int lane  = threadIdx.x & 31;
    if (gwarp >= NTOK) return;
    const float* xr = x + (size_t)gwarp * D_MODEL;

    float acc[NE];
#pragma unroll
    for (int e = 0; e < NE; e++) acc[e] = 0.f;
    for (int d = lane; d < D_MODEL; d += 32) {
        float xv = xr[d];
#pragma unroll
        for (int e = 0; e < NE; e++) acc[e] += xv * gw[d * NE + e];
    }
#pragma unroll
    for (int e = 0; e < NE; e++) {
#pragma unroll
        for (int off = 16; off > 0; off >>= 1)
            acc[e] += __shfl_xor_sync(0xffffffffu, acc[e], off);
    }
    if (lane == 0) {
        float mx = acc[0];
#pragma unroll
        for (int e = 1; e < NE; e++) mx = fmaxf(mx, acc[e]);
        float p[NE];
#pragma unroll
        for (int e = 0; e < NE; e++) p[e] = __expf(acc[e] - mx);
        int i0 = 0;
#pragma unroll
        for (int e = 1; e < NE; e++) if (p[e] > p[i0]) i0 = e;
        int i1 = (i0 == 0) ? 1 : 0;
#pragma unroll
        for (int e = 0; e < NE; e++) if (e != i0 && p[e] > p[i1]) i1 = e;
        float s2 = p[i0] + p[i1];
        int pr0 = gwarp * 2, pr1 = gwarp * 2 + 1;
        g_wgt[pr0] = p[i0] / s2;
        g_wgt[pr1] = p[i1] / s2;
        int pos0 = atomicAdd(&g_cnt[i0], 1);
        g_list[i0 * MAXPER + pos0] = pr0;
        int pos1 = atomicAdd(&g_cnt[i1], 1);
        g_list[i1 * MAXPER + pos1] = pr1;
    }
}

// ======================= pipelined tf32 MMA GEMM bodies ========================
// Per CTA: 128x128 tile, 256 thr / 8 warps (2x4), warp tile 64x32, KC=32.
// A (gathered rows, already tf32 bits) and B (weights, k-major [k][n], cvt at
// fragment load) stream through a 3-stage cp.async ring.

struct PipeCtx {
    const float* arow;    // this thread's A source row (+khalf offset)
    uint32_t aval;        // 16 or 0 (zfill)
    const float* bcol;    // weight base + n0 + (t&31)*4
    int ldb;
    uint32_t a_s;         // smem byte offset of this thread's A dst (stage 0)
    uint32_t b_s;         // smem byte offset of this thread's B dst (stage 0)
};

__device__ __forceinline__ void pipe_load(const PipeCtx& P, int ic, int st) {
    uint32_t as = P.a_s + st * (STAGE_W * 4);
    const float* ag = P.arow + ic * 32;
#pragma unroll
    for (int q = 0; q < 4; q++) cpa16(as + q * 16, ag + q * 4, P.aval);
    uint32_t bs = P.b_s + st * (STAGE_W * 4);
    const float* bg = P.bcol + (size_t)ic * 32 * P.ldb;
#pragma unroll
    for (int kq = 0; kq < 4; kq++)
        cpa16(bs + kq * (8 * LDB * 4), bg + (size_t)kq * 8 * P.ldb, 16);
    cpa_commit();
}

#define PIPE_SETUP(ATYPE_PTR, LDB_V, BW_PTR)                                     \
    extern __shared__ uint32_t smw[];                                            \
    const int tid  = threadIdx.x;                                                \
    const int lane = tid & 31, wid = tid >> 5;                                   \
    const int wm0 = (wid >> 2) * 64, wn0 = (wid & 3) * 32;                       \
    int* s_pair = (int*)smw;                                                     \
    if (tid < 128) {                                                             \
        int gm = m0 + tid;                                                       \
        s_pair[tid] = (gm < cnt) ? g_list[e * MAXPER + gm] : -1;                 \
    }                                                                            \
    __syncthreads();                                                             \
    PipeCtx P;                                                                   \
    {                                                                            \
        uint32_t sb = smem_u32(smw);                                             \
        P.ldb  = (LDB_V);                                                        \
        P.aval = 0; P.arow = ATYPE_PTR; /* set below */                          \
        P.bcol = (BW_PTR) + n0 + (tid & 31) * 4 + (size_t)(tid >> 5) * (LDB_V);  \
        P.a_s  = sb + SP_W * 4 + (tid >> 1) * (LDA * 4) + (tid & 1) * 64;        \
        P.b_s  = sb + SP_W * 4 + A_ST_W * 4 + (tid >> 5) * (LDB * 4) +           \
                 (tid & 31) * 16;                                                \
    }

#define PIPE_MAINLOOP(NC)                                                        \
    float acc[4][4][4];                                                          \
    _Pragma("unroll") for (int a_ = 0; a_ < 4; a_++)                             \
    _Pragma("unroll") for (int b_ = 0; b_ < 4; b_++)                             \
    _Pragma("unroll") for (int c_ = 0; c_ < 4; c_++) acc[a_][b_][c_] = 0.f;      \
    pipe_load(P, 0, 0); pipe_load(P, 1, 1); pipe_load(P, 2, 2);                  \
    for (int i = 0; i < (NC); i++) {                                             \
        int st = i % 3;                                                          \
        cpa_wait2();                                                             \
        __syncthreads();                                                         \
        const uint32_t* sA = smw + SP_W + st * STAGE_W;                          \
        const uint32_t* sB = smw + SP_W + st * STAGE_W + A_ST_W;                 \
        _Pragma("unroll")                                                        \
        for (int ks = 0; ks < 32; ks += 8) {                                     \
            uint32_t bf0[4], bf1[4];                                             \
            _Pragma("unroll")                                                    \
            for (int ni = 0; ni < 4; ni++) {                                     \
                int cB = wn0 + ni * 8 + (lane >> 2);                             \
                bf0[ni] = bits2tf32(sB[(ks +     (lane & 3)) * LDB + cB]);       \
                bf1[ni] = bits2tf32(sB[(ks + 4 + (lane & 3)) * LDB + cB]);       \
            }                                                                    \
            _Pragma("unroll")                                                    \
            for (int mi = 0; mi < 4; mi++) {                                     \
                int rA = wm0 + mi * 16 + (lane >> 2);                            \
                uint32_t a0 = sA[rA * LDA + ks + (lane & 3)];                    \
                uint32_t a1 = sA[(rA + 8) * LDA + ks + (lane & 3)];              \
                uint32_t a2 = sA[rA * LDA + ks + 4 + (lane & 3)];                \
                uint32_t a3 = sA[(rA + 8) * LDA + ks + 4 + (lane & 3)];          \
                _Pragma("unroll")                                                \
                for (int ni = 0; ni < 4; ni++)                                   \
                    mma_tf32(acc[mi][ni], a0, a1, a2, a3, bf0[ni], bf1[ni]);     \
            }                                                                    \
        }                                                                        \
        __syncthreads();                                                         \
        if (i + 3 < (NC)) pipe_load(P, i + 3, st); else cpa_commit();            \
    }

// ---------------- GEMM1: g_h = tf32(gelu(x_g @ W1_e + b1_e)) -------------------
__global__ __launch_bounds__(256, 2)
void gemm1_mma(const float* __restrict__ w1, const float* __restrict__ b1) {
    const int e   = blockIdx.z;
    const int cnt = g_cnt[e];
    const int m0  = blockIdx.y * 128;
    if (m0 >= cnt) return;
    const int n0  = blockIdx.x * 128;

    PIPE_SETUP((const float*)0, D_HID, (w1 + (size_t)e * D_MODEL * D_HID));
    {
        int pr = s_pair[tid >> 1];
        P.aval = (pr >= 0) ? 16u : 0u;
        P.arow = g_x + (size_t)((pr >= 0) ? (pr >> 1) : 0) * D_MODEL +
                 (tid & 1) * 16;
    }
    PIPE_MAINLOOP(D_MODEL / 32)

    // epilogue: bias + erf-GELU, tf32-rounded -> g_h
#pragma unroll
    for (int mi = 0; mi < 4; mi++) {
        int r0 = wm0 + mi * 16 + (lane >> 2);
#pragma unroll
        for (int half = 0; half < 2; half++) {
            int r = r0 + half * 8;
            int pr = s_pair[r];
            if (pr < 0) continue;
            float* hrow = g_h + (size_t)pr * D_HID + n0;
#pragma unroll
            for (int ni = 0; ni < 4; ni++) {
                int c = wn0 + ni * 8 + 2 * (lane & 3);
                float2 bb = *(const float2*)(b1 + e * D_HID + n0 + c);
                float2 o;
                o.x = __uint_as_float(f2tf32(gelu_f(acc[mi][ni][half * 2 + 0] + bb.x)));
                o.y = __uint_as_float(f2tf32(gelu_f(acc[mi][ni][half * 2 + 1] + bb.y)));
                *(float2*)(hrow + c) = o;
            }
        }
    }
}

// ---------------- GEMM2: out += wgt * (g_h @ W2_e + b2_e) ----------------------
__global__ __launch_bounds__(256, 2)
void gemm2_mma(const float* __restrict__ w2, const float* __restrict__ b2,
               float* __restrict__ out) {
    const int e   = blockIdx.z;
    const int cnt = g_cnt[e];
    const int m0  = blockIdx.y * 128;
    if (m0 >= cnt) return;
    const int n0  = blockIdx.x * 128;

    PIPE_SETUP((const float*)0, D_MODEL, (w2 + (size_t)e * D_HID * D_MODEL));
    {
        int pr = s_pair[tid >> 1];
        P.aval = (pr >= 0) ? 16u : 0u;
        P.arow = g_h + (size_t)((pr >= 0) ? pr : 0) * D_HID + (tid & 1) * 16;
    }
    PIPE_MAINLOOP(D_HID / 32)

    // epilogue: (acc + b2) * wgt -> atomicAdd out
#pragma unroll
    for (int mi = 0; mi < 4; mi++) {
        int r0 = wm0 + mi * 16 + (lane >> 2);
#pragma unroll
        for (int half = 0; half < 2; half++) {
            int r = r0 + half * 8;
            int pr = s_pair[r];
            if (pr < 0) continue;
            int tok = pr >> 1;
            float w = g_wgt[pr];
            float* orow = out + (size_t)tok * D_MODEL + n0;
#pragma unroll
            for (int ni = 0; ni < 4; ni++) {
                int c = wn0 + ni * 8 + 2 * (lane & 3);
                float2 bb = *(const float2*)(b2 + e * D_MODEL + n0 + c);
                atomicAdd(&orow[c],     (acc[mi][ni][half * 2 + 0] + bb.x) * w);
                atomicAdd(&orow[c + 1], (acc[mi][ni][half * 2 + 1] + bb.y) * w);
            }
        }
    }
}

// ---------------- launch ------------------------------------------------------
extern "C" void kernel_launch(void* const* d_in, const int* in_sizes, int n_in,
                              void* d_out, int out_size) {
    const float* x  = (const float*)d_in[0];
    const float* gw = (const float*)d_in[1];
    const float* w1 = (const float*)d_in[2];
    const float* b1 = (const float*)d_in[3];
    const float* w2 = (const float*)d_in[4];
    const float* b2 = (const float*)d_in[5];
    float* out = (float*)d_out;

    cudaFuncSetAttribute(gemm1_mma, cudaFuncAttributeMaxDynamicSharedMemorySize, SMEM_BYTES);
    cudaFuncSetAttribute(gemm2_mma, cudaFuncAttributeMaxDynamicSharedMemorySize, SMEM_BYTES);

    init_kernel<<<(NTOK * D_MODEL / 4) / 256, 256>>>(out, x);
    router_kernel<<<NTOK / 8, 256>>>(x, gw);
    gemm1_mma<<<dim3(D_HID / 128, MAXPER / 128, NE), 256, SMEM_BYTES>>>(w1, b1);
    gemm2_mma<<<dim3(D_MODEL / 128, MAXPER / 128, NE), 256, SMEM_BYTES>>>(w2, b2, out);
}